// round 2
// baseline (speedup 1.0000x reference)
#include <cuda_runtime.h>

// Problem constants (from reference: B=2048, N=64, D=256, 4 steps)
#define BB      2048
#define NN      64
#define DD      256
#define NSTEPS  4
#define ROWS    64            // batch rows per CTA
#define XS_STRIDE 260         // padded row stride (mult of 4 for float4, not mult of 32)
#define THREADS 256

// Scratch (device globals; no allocation allowed)
__device__ float g_wt[NN * DD * DD];   // masked, transposed weights: wt[n][i][j] = w[n][j][i]*mask
__device__ float g_b[NN * DD];         // masked biases
__device__ int   g_nact[NN];           // active width per group

// ---------------------------------------------------------------------------
// Premask + transpose weights: wt[n][i][j] = w[n][j][i] * wmask[n][j][i]
// grid (8, 8, 64), block (32, 8)
// ---------------------------------------------------------------------------
__global__ void premask_transpose_kernel(const float* __restrict__ w,
                                         const float* __restrict__ wm) {
    __shared__ float t[32][33];
    const int n = blockIdx.z, bi = blockIdx.x, bj = blockIdx.y;
    const int tx = threadIdx.x, ty = threadIdx.y;
#pragma unroll
    for (int k = 0; k < 4; ++k) {
        int j = bj * 32 + ty + k * 8;
        int i = bi * 32 + tx;
        size_t idx = ((size_t)n * DD + j) * DD + i;
        t[ty + k * 8][tx] = w[idx] * wm[idx];
    }
    __syncthreads();
#pragma unroll
    for (int k = 0; k < 4; ++k) {
        int i = bi * 32 + ty + k * 8;
        int j = bj * 32 + tx;
        g_wt[((size_t)n * DD + i) * DD + j] = t[tx][ty + k * 8];
    }
}

// ---------------------------------------------------------------------------
// Premask bias + count active columns per group. grid 64, block 256.
// ---------------------------------------------------------------------------
__global__ void premask_bias_kernel(const float* __restrict__ b,
                                    const float* __restrict__ bm) {
    const int n = blockIdx.x, t = threadIdx.x;
    __shared__ int cnt;
    if (t == 0) cnt = 0;
    __syncthreads();
    float m = bm[n * DD + t];
    g_b[n * DD + t] = b[n * DD + t] * m;
    if (m != 0.f) atomicAdd(&cnt, 1);
    __syncthreads();
    if (t == 0) g_nact[n] = cnt;
}

// ---------------------------------------------------------------------------
// Fused 4-step recurrence. Templated on NK = n_act/32 (0 => runtime bound).
// Thread (tr, tc): owns rows tr*8..tr*8+7, cols tc + 32*jj.
// ---------------------------------------------------------------------------
template <int NK>
__device__ __forceinline__ void run_steps(float* __restrict__ xs,
                                          float* __restrict__ ws,
                                          const float* __restrict__ bs,
                                          const float* __restrict__ wt_n,
                                          int nk_rt, int tr, int tc) {
    const int nkk = (NK > 0) ? NK : nk_rt;
    const int tid = tr * 32 + tc;

    for (int step = 0; step < NSTEPS; ++step) {
        float acc[8][8];
#pragma unroll
        for (int m = 0; m < 8; ++m)
#pragma unroll
            for (int jj = 0; jj < 8; ++jj) acc[m][jj] = 0.f;

        for (int kc = 0; kc < nkk; ++kc) {
            __syncthreads();   // prior-chunk compute done (and prior-step xs writes visible)
            {
                // Stage 32 x 256 contiguous chunk of wt[n] into SMEM (float4, coalesced)
                const float4* src = (const float4*)(wt_n + kc * 32 * DD);
                float4* dst = (float4*)ws;
#pragma unroll
                for (int v = 0; v < 8; ++v)
                    dst[tid + v * THREADS] = src[tid + v * THREADS];
            }
            __syncthreads();

#pragma unroll 4
            for (int i = 0; i < 32; ++i) {
                float xv[8];
#pragma unroll
                for (int m = 0; m < 8; ++m)   // warp-broadcast LDS
                    xv[m] = xs[(tr * 8 + m) * XS_STRIDE + kc * 32 + i];
#pragma unroll
                for (int jj = 0; jj < ((NK > 0) ? NK : 8); ++jj) {
                    if (NK == 0 && jj >= nk_rt) break;
                    float wv = ws[i * DD + tc + 32 * jj];   // bank = lane: conflict-free
#pragma unroll
                    for (int m = 0; m < 8; ++m)
                        acc[m][jj] = fmaf(xv[m], wv, acc[m][jj]);
                }
            }
        }

        // Epilogue: x += relu(acc + b). Rows are warp-exclusive; the sync at the
        // top of the next chunk/store covers cross-lane col visibility.
#pragma unroll
        for (int jj = 0; jj < ((NK > 0) ? NK : 8); ++jj) {
            if (NK == 0 && jj >= nk_rt) break;
            int j = tc + 32 * jj;
            float bv = bs[j];
#pragma unroll
            for (int m = 0; m < 8; ++m) {
                float y = acc[m][jj] + bv;
                y = fmaxf(y, 0.f);
                xs[(tr * 8 + m) * XS_STRIDE + j] += y;
            }
        }
    }
}

extern __shared__ float smem[];

__global__ __launch_bounds__(THREADS, 2)
void batch_linear_fused_kernel(const float* __restrict__ x_in,
                               float* __restrict__ x_out) {
    float* xs = smem;                            // ROWS * XS_STRIDE
    float* ws = smem + ROWS * XS_STRIDE;         // 32 * DD
    float* bs = ws + 32 * DD;                    // DD

    const int tid = threadIdx.x;
    const int tr = tid >> 5, tc = tid & 31;
    const int n = blockIdx.x >> 5;               // 64 groups x 32 batch-tiles
    const int btile = blockIdx.x & 31;
    const int r0 = btile * ROWS;

    bs[tid] = g_b[n * DD + tid];

    // Load x tile: 64 rows x 256 floats, float4 coalesced
    {
        const float4* src = (const float4*)x_in;
        for (int v = tid; v < ROWS * DD / 4; v += THREADS) {
            int row = v >> 6;   // 64 float4 per row
            int c4 = v & 63;
            float4 val = src[((((size_t)(r0 + row) * NN + n) * DD) >> 2) + c4];
            *(float4*)&xs[row * XS_STRIDE + c4 * 4] = val;
        }
    }
    int nact = g_nact[n];
    int nk = (nact + 31) >> 5;   // K/j chunk count (masked-zero overshoot is harmless)
    __syncthreads();

    const float* wt_n = g_wt + (size_t)n * DD * DD;
    switch (nk) {
        case 4: run_steps<4>(xs, ws, bs, wt_n, nk, tr, tc); break;
        case 5: run_steps<5>(xs, ws, bs, wt_n, nk, tr, tc); break;
        case 6: run_steps<6>(xs, ws, bs, wt_n, nk, tr, tc); break;
        case 7: run_steps<7>(xs, ws, bs, wt_n, nk, tr, tc); break;
        case 8: run_steps<8>(xs, ws, bs, wt_n, nk, tr, tc); break;
        default: run_steps<0>(xs, ws, bs, wt_n, nk, tr, tc); break;
    }

    __syncthreads();   // xs fully updated by all warps before cross-row store

    // Store result tile
    {
        float4* dst = (float4*)x_out;
        for (int v = tid; v < ROWS * DD / 4; v += THREADS) {
            int row = v >> 6;
            int c4 = v & 63;
            dst[((((size_t)(r0 + row) * NN + n) * DD) >> 2) + c4] =
                *(const float4*)&xs[row * XS_STRIDE + c4 * 4];
        }
    }
}

// ---------------------------------------------------------------------------
// Launch
// ---------------------------------------------------------------------------
extern "C" void kernel_launch(void* const* d_in, const int* in_sizes, int n_in,
                              void* d_out, int out_size) {
    const float* x  = (const float*)d_in[0];
    const float* w  = (const float*)d_in[1];
    const float* b  = (const float*)d_in[2];
    const float* wm = (const float*)d_in[3];
    const float* bm = (const float*)d_in[4];
    float* out = (float*)d_out;

    const int smem_bytes = (ROWS * XS_STRIDE + 32 * DD + DD) * sizeof(float); // 100,352 B
    cudaFuncSetAttribute(batch_linear_fused_kernel,
                         cudaFuncAttributeMaxDynamicSharedMemorySize, smem_bytes);

    premask_transpose_kernel<<<dim3(8, 8, NN), dim3(32, 8)>>>(w, wm);
    premask_bias_kernel<<<NN, 256>>>(b, bm);
    batch_linear_fused_kernel<<<NN * (BB / ROWS), THREADS, smem_bytes>>>(x, out);
}

// round 4
// speedup vs baseline: 2.3600x; 2.3600x over previous
#include <cuda_runtime.h>
#include <cstdint>

#define BB      2048
#define NN      64
#define DD      256
#define NSTEPS  4
#define MTILE   128            // batch rows per CTA
#define THREADS 512            // 16 warps: 4 (M) x 4 (N)
#define XS_STRIDE 260          // % 32 == 4 -> conflict-free A-fragment LDS

// SMEM layout (floats)
#define XS_FLOATS   (MTILE * XS_STRIDE)            // 33280
#define WBUF_FLOATS 4096                           // one K16 chunk (max): 32 tiles * 128
#define BIAS_OFF    (XS_FLOATS + 2 * WBUF_FLOATS)  // 41472
#define SMEM_FLOATS (BIAS_OFF + DD)                // 41728 -> 166912 B

// Scratch (device globals; no allocation allowed)
// g_wfrag[n][kc][t][lane][w]: masked W in tf32 bits, m16n8k8 B-fragment order.
//   kc = i>>4 (K16 chunk), t = j>>3 (8-col n-tile), lane = (j&7)*4 + (i&3),
//   w  = ((i>>3)&1)*2 + ((i>>2)&1)   (i.e. [k8-step s][b0/b1])
__device__ __align__(16) uint32_t g_wfrag[NN * 65536];
__device__ float g_b[NN * DD];
__device__ int   g_nact[NN];

// ---------------------------------------------------------------------------
// PTX helpers (all plain sm_80+ PTX — no 'a'-gated features)
// ---------------------------------------------------------------------------
__device__ __forceinline__ uint32_t f2tf32(float v) {
    uint32_t r;
    asm("cvt.rna.tf32.f32 %0, %1;" : "=r"(r) : "f"(v));
    return r;
}

__device__ __forceinline__ void mma1688(float* d, const uint32_t* a,
                                        uint32_t b0, uint32_t b1) {
    asm volatile(
        "mma.sync.aligned.m16n8k8.row.col.f32.tf32.tf32.f32 "
        "{%0,%1,%2,%3}, {%4,%5,%6,%7}, {%8,%9}, {%0,%1,%2,%3};"
        : "+f"(d[0]), "+f"(d[1]), "+f"(d[2]), "+f"(d[3])
        : "r"(a[0]), "r"(a[1]), "r"(a[2]), "r"(a[3]), "r"(b0), "r"(b1));
}

__device__ __forceinline__ void cp16(uint32_t s_dst, const void* g_src) {
    asm volatile("cp.async.cg.shared.global [%0], [%1], 16;"
                 :: "r"(s_dst), "l"(g_src) : "memory");
}
__device__ __forceinline__ void cp_commit() {
    asm volatile("cp.async.commit_group;" ::: "memory");
}
__device__ __forceinline__ void cp_wait0() {
    asm volatile("cp.async.wait_group 0;" ::: "memory");
}

// ---------------------------------------------------------------------------
// Prep: premask W, convert to tf32 (RNA), scatter into B-fragment layout
// ---------------------------------------------------------------------------
__global__ void wfrag_prep_kernel(const float* __restrict__ w,
                                  const float* __restrict__ wm) {
    int idx = blockIdx.x * 256 + threadIdx.x;     // exactly NN*DD*DD threads
    float v = w[idx] * wm[idx];
    uint32_t tv = f2tf32(v);
    int n = idx >> 16, rem = idx & 65535;
    int j = rem >> 8, i = rem & 255;
    int kc = i >> 4, ib = i & 15;
    int t = j >> 3;
    int lane = ((j & 7) << 2) | (ib & 3);
    int wv = ((ib >> 3) << 1) | ((ib >> 2) & 1);
    g_wfrag[(n << 16) | (kc << 12) | (t << 7) | (lane << 2) | wv] = tv;
}

__global__ void premask_bias_kernel(const float* __restrict__ b,
                                    const float* __restrict__ bm) {
    const int n = blockIdx.x, t = threadIdx.x;
    __shared__ int cnt;
    if (t == 0) cnt = 0;
    __syncthreads();
    float m = bm[n * DD + t];
    g_b[n * DD + t] = b[n * DD + t] * m;
    if (m != 0.f) atomicAdd(&cnt, 1);
    __syncthreads();
    if (t == 0) g_nact[n] = cnt;
}

// ---------------------------------------------------------------------------
// Fused 4-step recurrence via mma.sync tf32 (tensor pipe, sm_103-legal PTX)
// ---------------------------------------------------------------------------
extern __shared__ __align__(16) float smem[];

__global__ __launch_bounds__(THREADS, 1)
void blm_mma_kernel(const float* __restrict__ x_in, float* __restrict__ x_out) {
    float* xs = smem;
    float* bsm = smem + BIAS_OFF;
    const uint32_t smem_u = (uint32_t)__cvta_generic_to_shared(smem);
    const uint32_t wb_u = smem_u + XS_FLOATS * 4;

    const int tid = threadIdx.x;
    const int wid = tid >> 5, lane = tid & 31;
    const int mi = wid & 3, ni = wid >> 2;
    const int n = blockIdx.x >> 4;          // 64 groups x 16 batch tiles
    const int r0 = (blockIdx.x & 15) * MTILE;

    if (tid < DD) bsm[tid] = g_b[n * DD + tid];

    // Load x tile (128 x 256), plain row-major stride 260
    {
        const float4* xin4 = (const float4*)x_in;
        for (int v = tid; v < MTILE * 64; v += THREADS) {
            int row = v >> 6, c4 = v & 63;
            *(float4*)&xs[row * XS_STRIDE + c4 * 4] =
                xin4[((size_t)(r0 + row) * NN + n) * 64 + c4];
        }
    }

    const int nact = g_nact[n];
    const int nkc = nact >> 4;      // K16 chunks
    const int ntpw = nact >> 5;     // 8-wide n-tiles per warp (4..8)
    const int nf4 = (nact >> 3) << 5;   // float4 count per W chunk
    const uint32_t* wsrc = g_wfrag + ((size_t)n << 16);

    const int rA = mi * 32 + (lane >> 2);       // A-frag base row
    const int cq = 2 * (lane & 3);              // C-frag col pair offset
    const int nbase = ni * (nact >> 2);         // warp's first output col

    __syncthreads();

    float acc[2][8][4];

    for (int step = 0; step < NSTEPS; ++step) {
#pragma unroll
        for (int mt = 0; mt < 2; ++mt)
#pragma unroll
            for (int t = 0; t < 8; ++t)
#pragma unroll
                for (int q = 0; q < 4; ++q) acc[mt][t][q] = 0.f;

        // preload chunk 0
        {
            const float4* src = (const float4*)wsrc;
            for (int v = tid; v < nf4; v += THREADS) cp16(wb_u + v * 16, src + v);
            cp_commit(); cp_wait0();
            __syncthreads();
        }

        for (int kc = 0; kc < nkc; ++kc) {
            const int buf = kc & 1;
            if (kc + 1 < nkc) {      // prefetch next chunk into other buffer
                const float4* src = (const float4*)(wsrc + ((kc + 1) << 12));
                const uint32_t dst = wb_u + (buf ^ 1) * (WBUF_FLOATS * 4);
                for (int v = tid; v < nf4; v += THREADS) cp16(dst + v * 16, src + v);
                cp_commit();
            }

            // A fragments: 2 k8-steps x 2 m-tiles, RNA-converted to tf32
            uint32_t a[2][2][4];
            const int c0 = kc * 16 + (lane & 3);
#pragma unroll
            for (int s = 0; s < 2; ++s)
#pragma unroll
                for (int mt = 0; mt < 2; ++mt) {
                    const int r = rA + mt * 16;
                    const int c = c0 + s * 8;
                    a[s][mt][0] = f2tf32(xs[r * XS_STRIDE + c]);
                    a[s][mt][1] = f2tf32(xs[(r + 8) * XS_STRIDE + c]);
                    a[s][mt][2] = f2tf32(xs[r * XS_STRIDE + c + 4]);
                    a[s][mt][3] = f2tf32(xs[(r + 8) * XS_STRIDE + c + 4]);
                }

            // B fragments: one LDS.128 per n-tile (pre-packed), 4 MMAs each
            const uint4* bp = (const uint4*)(smem + XS_FLOATS + buf * WBUF_FLOATS)
                              + ni * ntpw * 32 + lane;
#pragma unroll
            for (int t = 0; t < 8; ++t) {
                if (t >= ntpw) break;
                uint4 b = bp[t * 32];
                mma1688(acc[0][t], a[0][0], b.x, b.y);
                mma1688(acc[1][t], a[0][1], b.x, b.y);
                mma1688(acc[0][t], a[1][0], b.z, b.w);
                mma1688(acc[1][t], a[1][1], b.z, b.w);
            }

            if (kc + 1 < nkc) cp_wait0();
            __syncthreads();   // chunk consumed; last iter: all A reads done
        }

        // Epilogue: x += relu(acc + b); warps own disjoint 32 x (nact/4) tiles
#pragma unroll
        for (int mt = 0; mt < 2; ++mt) {
            const int r = rA + mt * 16;
#pragma unroll
            for (int t = 0; t < 8; ++t) {
                if (t >= ntpw) break;
                const int c = nbase + t * 8 + cq;
                const float b0 = bsm[c], b1 = bsm[c + 1];
                float2* p0 = (float2*)&xs[r * XS_STRIDE + c];
                float2 v0 = *p0;
                v0.x += fmaxf(acc[mt][t][0] + b0, 0.f);
                v0.y += fmaxf(acc[mt][t][1] + b1, 0.f);
                *p0 = v0;
                float2* p1 = (float2*)&xs[(r + 8) * XS_STRIDE + c];
                float2 v1 = *p1;
                v1.x += fmaxf(acc[mt][t][2] + b0, 0.f);
                v1.y += fmaxf(acc[mt][t][3] + b1, 0.f);
                *p1 = v1;
            }
        }
        __syncthreads();
    }

    // Store full tile (cols >= nact pass through untouched = mask semantics)
    {
        float4* xo = (float4*)x_out;
        for (int v = tid; v < MTILE * 64; v += THREADS) {
            int row = v >> 6, c4 = v & 63;
            xo[((size_t)(r0 + row) * NN + n) * 64 + c4] =
                *(const float4*)&xs[row * XS_STRIDE + c4 * 4];
        }
    }
}

// ---------------------------------------------------------------------------
// Launch
// ---------------------------------------------------------------------------
extern "C" void kernel_launch(void* const* d_in, const int* in_sizes, int n_in,
                              void* d_out, int out_size) {
    const float* x  = (const float*)d_in[0];
    const float* w  = (const float*)d_in[1];
    const float* b  = (const float*)d_in[2];
    const float* wm = (const float*)d_in[3];
    const float* bm = (const float*)d_in[4];
    float* out = (float*)d_out;

    const int smem_bytes = SMEM_FLOATS * 4;   // 166912
    cudaFuncSetAttribute(blm_mma_kernel,
                         cudaFuncAttributeMaxDynamicSharedMemorySize, smem_bytes);

    wfrag_prep_kernel<<<NN * DD * DD / 256, 256>>>(w, wm);
    premask_bias_kernel<<<NN, 256>>>(b, bm);
    blm_mma_kernel<<<NN * (BB / MTILE), THREADS, smem_bytes>>>(x, out);
}

// round 6
// speedup vs baseline: 3.1042x; 1.3153x over previous
#include <cuda_runtime.h>
#include <cuda_fp16.h>
#include <cstdint>

#define BB      2048
#define NN      64
#define DD      256
#define NSTEPS  4
#define MTILE   128            // batch rows per CTA
#define THREADS 512            // 16 warps: 4 (M) x 4 (N)
#define XS_STRIDE 260          // % 32 == 4 -> conflict-free A-fragment LDS

// SMEM layout (floats)
#define XS_FLOATS   (MTILE * XS_STRIDE)            // 33280 -> 133120 B
#define WBUF_U2     2048                           // uint2 per buffer (16 KB max stage)
#define WBUF_OFF    XS_FLOATS                      // in floats
#define BIAS_OFF    (XS_FLOATS + 2 * WBUF_U2 * 2)  // 41472 floats
#define SMEM_FLOATS (BIAS_OFF + DD)                // 41728 -> 166912 B

// Scratch (device globals; no allocation allowed)
// g_wpack[n][kc16][t][lane] (uint2 = {b0:half2, b1:half2}): masked W in fp16,
// m16n8k16 B-fragment order. j = t*8 + (lane>>2); i = kc*16 + 2*(lane&3) (+1,+8,+9).
// Granule stride (kc16): 32 tiles * 32 lanes = 1024 uint2, ALWAYS full 32 tiles.
__device__ __align__(16) uint2 g_wpack[NN * 16 * 32 * 32];
__device__ float g_b[NN * DD];
__device__ int   g_nact[NN];

// ---------------------------------------------------------------------------
// PTX helpers (plain sm_80+ PTX only — sm_103 target has no 'a' features)
// ---------------------------------------------------------------------------
__device__ __forceinline__ void mma16816(float* d, const uint32_t* a,
                                         uint32_t b0, uint32_t b1) {
    asm volatile(
        "mma.sync.aligned.m16n8k16.row.col.f32.f16.f16.f32 "
        "{%0,%1,%2,%3}, {%4,%5,%6,%7}, {%8,%9}, {%0,%1,%2,%3};"
        : "+f"(d[0]), "+f"(d[1]), "+f"(d[2]), "+f"(d[3])
        : "r"(a[0]), "r"(a[1]), "r"(a[2]), "r"(a[3]), "r"(b0), "r"(b1));
}

__device__ __forceinline__ void cp16(uint32_t s_dst, const void* g_src) {
    asm volatile("cp.async.cg.shared.global [%0], [%1], 16;"
                 :: "r"(s_dst), "l"(g_src) : "memory");
}
__device__ __forceinline__ void cp_commit() {
    asm volatile("cp.async.commit_group;" ::: "memory");
}
__device__ __forceinline__ void cp_wait0() {
    asm volatile("cp.async.wait_group 0;" ::: "memory");
}

__device__ __forceinline__ uint32_t h2u(__half2 h) {
    return *(uint32_t*)&h;
}

// ---------------------------------------------------------------------------
// Prep: premask W -> fp16 B-fragments; last 64 blocks do bias + nact
// ---------------------------------------------------------------------------
__global__ void prep_kernel(const float* __restrict__ w,
                            const float* __restrict__ wm,
                            const float* __restrict__ b,
                            const float* __restrict__ bm) {
    if (blockIdx.x >= 4096) {                       // bias part
        const int n = blockIdx.x - 4096, t = threadIdx.x;
        __shared__ int cnt;
        if (t == 0) cnt = 0;
        __syncthreads();
        float m = bm[n * DD + t];
        g_b[n * DD + t] = b[n * DD + t] * m;
        if (m != 0.f) atomicAdd(&cnt, 1);
        __syncthreads();
        if (t == 0) g_nact[n] = cnt;
        return;
    }
    int q = blockIdx.x * 256 + threadIdx.x;         // [0, 64*16*32*32)
    int lane = q & 31, t = (q >> 5) & 31, kc = (q >> 10) & 15, n = q >> 14;
    int j = t * 8 + (lane >> 2);
    int i0 = kc * 16 + 2 * (lane & 3);
    size_t base = ((size_t)n * DD + j) * DD + i0;
    float2 vlo = *(const float2*)(w + base);
    float2 mlo = *(const float2*)(wm + base);
    float2 vhi = *(const float2*)(w + base + 8);
    float2 mhi = *(const float2*)(wm + base + 8);
    uint2 r;
    r.x = h2u(__floats2half2_rn(vlo.x * mlo.x, vlo.y * mlo.y));
    r.y = h2u(__floats2half2_rn(vhi.x * mhi.x, vhi.y * mhi.y));
    g_wpack[q] = r;
}

// ---------------------------------------------------------------------------
// Fused 4-step recurrence via mma.sync m16n8k16 fp16 (fp32 accumulate)
// ---------------------------------------------------------------------------
extern __shared__ __align__(16) float smem[];

// NT > 0: compile-time stage/tile count (nact/32); NT == 0: runtime (nt).
template <int NT>
__device__ __forceinline__ void run_steps(float* xs, float* bsm,
                                          const uint2* wsrc, uint32_t wb_u,
                                          int nt_rt, int tid, int wid, int lane) {
    const int nt = (NT > 0) ? NT : nt_rt;
    const int ntiles = nt * 4;                    // active 8-col n-tiles
    const int mi = wid & 3, ni = wid >> 2;
    const int rA = mi * 32 + (lane >> 2);
    const int cq = 2 * (lane & 3);
    const int nbase = ni * nt * 8;
    uint2* wbuf = (uint2*)(smem + WBUF_OFF);

    // Granule-aware compacting stage copy:
    //   src granules kc = 2s, 2s+1 (each 512 uint4, full 32 tiles);
    //   dst compact [sub][ntiles][lane] -> sub stride = ntiles*16 uint4.
    auto stage_copy = [&](int s, uint32_t dst) {
        const uint4* base = (const uint4*)wsrc + (size_t)s * 1024;
        const int half_u4 = ntiles * 16;
        for (int v = tid; v < 2 * half_u4; v += THREADS) {
            int sub = (v >= half_u4) ? 1 : 0;
            int within = v - sub * half_u4;
            cp16(dst + v * 16, base + sub * 512 + within);
        }
    };

    float acc[2][(NT > 0) ? NT : 8][4];

    for (int step = 0; step < NSTEPS; ++step) {
#pragma unroll
        for (int mt = 0; mt < 2; ++mt)
#pragma unroll
            for (int t = 0; t < ((NT > 0) ? NT : 8); ++t)
#pragma unroll
                for (int q = 0; q < 4; ++q)
                    if (NT > 0 || t < nt_rt) acc[mt][t][q] = 0.f;

        // preload stage 0
        stage_copy(0, wb_u);
        cp_commit(); cp_wait0();
        __syncthreads();

        for (int s = 0; s < nt; ++s) {
            const int buf = s & 1;
            if (s + 1 < nt) {
                stage_copy(s + 1, wb_u + (buf ^ 1) * (WBUF_U2 * 8));
                cp_commit();
            }

#pragma unroll
            for (int sub = 0; sub < 2; ++sub) {
                // A fragments (m16n8k16 row-major map), fp16-converted on load
                const int k0 = s * 32 + sub * 16;
                uint32_t a[2][4];
#pragma unroll
                for (int mt = 0; mt < 2; ++mt) {
                    const int r = rA + mt * 16;
                    float2 f0 = *(const float2*)&xs[r * XS_STRIDE + k0 + cq];
                    float2 f1 = *(const float2*)&xs[(r + 8) * XS_STRIDE + k0 + cq];
                    float2 f2 = *(const float2*)&xs[r * XS_STRIDE + k0 + cq + 8];
                    float2 f3 = *(const float2*)&xs[(r + 8) * XS_STRIDE + k0 + cq + 8];
                    a[mt][0] = h2u(__floats2half2_rn(f0.x, f0.y));
                    a[mt][1] = h2u(__floats2half2_rn(f1.x, f1.y));
                    a[mt][2] = h2u(__floats2half2_rn(f2.x, f2.y));
                    a[mt][3] = h2u(__floats2half2_rn(f3.x, f3.y));
                }
                // B fragments from compact stage: [sub][tile][lane]
                const uint2* bp = wbuf + buf * WBUF_U2 +
                                  (sub * ntiles + ni * nt) * 32 + lane;
#pragma unroll
                for (int t = 0; t < ((NT > 0) ? NT : 8); ++t) {
                    if (NT == 0 && t >= nt_rt) break;
                    uint2 bfr = bp[t * 32];
                    mma16816(acc[0][t], a[0], bfr.x, bfr.y);
                    mma16816(acc[1][t], a[1], bfr.x, bfr.y);
                }
            }

            if (s + 1 < nt) cp_wait0();
            __syncthreads();
        }

        // Epilogue: x += relu(acc + b); warps own disjoint 32 x (nact/4) tiles
#pragma unroll
        for (int mt = 0; mt < 2; ++mt) {
            const int r = rA + mt * 16;
#pragma unroll
            for (int t = 0; t < ((NT > 0) ? NT : 8); ++t) {
                if (NT == 0 && t >= nt_rt) break;
                const int c = nbase + t * 8 + cq;
                const float b0 = bsm[c], b1 = bsm[c + 1];
                float2* p0 = (float2*)&xs[r * XS_STRIDE + c];
                float2 v0 = *p0;
                v0.x += fmaxf(acc[mt][t][0] + b0, 0.f);
                v0.y += fmaxf(acc[mt][t][1] + b1, 0.f);
                *p0 = v0;
                float2* p1 = (float2*)&xs[(r + 8) * XS_STRIDE + c];
                float2 v1 = *p1;
                v1.x += fmaxf(acc[mt][t][2] + b0, 0.f);
                v1.y += fmaxf(acc[mt][t][3] + b1, 0.f);
                *p1 = v1;
            }
        }
        __syncthreads();
    }
}

__global__ __launch_bounds__(THREADS, 1)
void blm_mma_kernel(const float* __restrict__ x_in, float* __restrict__ x_out) {
    float* xs = smem;
    float* bsm = smem + BIAS_OFF;
    const uint32_t smem_u = (uint32_t)__cvta_generic_to_shared(smem);
    const uint32_t wb_u = smem_u + WBUF_OFF * 4;

    const int tid = threadIdx.x;
    const int wid = tid >> 5, lane = tid & 31;
    const int n = blockIdx.x >> 4;          // 64 groups x 16 batch tiles
    const int r0 = (blockIdx.x & 15) * MTILE;

    if (tid < DD) bsm[tid] = g_b[n * DD + tid];

    // Load x tile (128 x 256), row-major stride 260
    {
        const float4* xin4 = (const float4*)x_in;
        for (int v = tid; v < MTILE * 64; v += THREADS) {
            int row = v >> 6, c4 = v & 63;
            *(float4*)&xs[row * XS_STRIDE + c4 * 4] =
                xin4[((size_t)(r0 + row) * NN + n) * 64 + c4];
        }
    }

    const int nt = g_nact[n] >> 5;          // stages / tiles-per-warp (4..8)
    const uint2* wsrc = g_wpack + ((size_t)n << 14);
    __syncthreads();

    switch (nt) {
        case 4: run_steps<4>(xs, bsm, wsrc, wb_u, nt, tid, wid, lane); break;
        case 5: run_steps<5>(xs, bsm, wsrc, wb_u, nt, tid, wid, lane); break;
        case 6: run_steps<6>(xs, bsm, wsrc, wb_u, nt, tid, wid, lane); break;
        case 7: run_steps<7>(xs, bsm, wsrc, wb_u, nt, tid, wid, lane); break;
        case 8: run_steps<8>(xs, bsm, wsrc, wb_u, nt, tid, wid, lane); break;
        default: run_steps<0>(xs, bsm, wsrc, wb_u, nt, tid, wid, lane); break;
    }

    // Store full tile (cols >= nact pass through untouched = mask semantics)
    {
        float4* xo = (float4*)x_out;
        for (int v = tid; v < MTILE * 64; v += THREADS) {
            int row = v >> 6, c4 = v & 63;
            xo[((size_t)(r0 + row) * NN + n) * 64 + c4] =
                *(const float4*)&xs[row * XS_STRIDE + c4 * 4];
        }
    }
}

// ---------------------------------------------------------------------------
// Launch
// ---------------------------------------------------------------------------
extern "C" void kernel_launch(void* const* d_in, const int* in_sizes, int n_in,
                              void* d_out, int out_size) {
    const float* x  = (const float*)d_in[0];
    const float* w  = (const float*)d_in[1];
    const float* b  = (const float*)d_in[2];
    const float* wm = (const float*)d_in[3];
    const float* bm = (const float*)d_in[4];
    float* out = (float*)d_out;

    const int smem_bytes = SMEM_FLOATS * 4;   // 166912
    cudaFuncSetAttribute(blm_mma_kernel,
                         cudaFuncAttributeMaxDynamicSharedMemorySize, smem_bytes);

    prep_kernel<<<4096 + 64, 256>>>(w, wm, b, bm);
    blm_mma_kernel<<<NN * (BB / MTILE), THREADS, smem_bytes>>>(x, out);
}

// round 7
// speedup vs baseline: 3.5500x; 1.1436x over previous
#include <cuda_runtime.h>
#include <cuda_fp16.h>
#include <cstdint>

#define BB      2048
#define NN      64
#define DD      256
#define NSTEPS  4
#define MTILE   64             // batch rows per CTA
#define THREADS 256            // 8 warps: 2 (M) x 4 (N)
#define XSH     264            // xs_h row stride in halfs (528B -> ldmatrix conflict-free)

// SMEM layout (bytes)
#define XSH_BYTES  (MTILE * XSH * 2)      // 33792
#define BIAS_OFF   XSH_BYTES              // 1024 B fp32
#define WBUF_OFF   (BIAS_OFF + 1024)      // 34816, then 2 * NT * 2048 bytes

// Scratch (device globals)
// g_wpack[n][kc32][t][lane] (uint4): masked W fp16, m16n8k16 B-frag order.
//   j = t*8 + (lane>>2); i0 = kc32*32 + 2*(lane&3);
//   .x=(i0,i0+1) .y=(+8,+9)  [sub0 b0,b1];  .z=(+16,+17) .w=(+24,+25) [sub1]
__device__ __align__(16) uint4 g_wpack[NN * 8 * 32 * 32];
__device__ float g_b[NN * DD];
__device__ int   g_nact[NN];

// ---------------------------------------------------------------------------
// PTX helpers (plain sm_80+ PTX)
// ---------------------------------------------------------------------------
__device__ __forceinline__ void mma16816(float* d, const uint32_t* a,
                                         uint32_t b0, uint32_t b1) {
    asm volatile(
        "mma.sync.aligned.m16n8k16.row.col.f32.f16.f16.f32 "
        "{%0,%1,%2,%3}, {%4,%5,%6,%7}, {%8,%9}, {%0,%1,%2,%3};"
        : "+f"(d[0]), "+f"(d[1]), "+f"(d[2]), "+f"(d[3])
        : "r"(a[0]), "r"(a[1]), "r"(a[2]), "r"(a[3]), "r"(b0), "r"(b1));
}
__device__ __forceinline__ void ldmatrix4(uint32_t* a, uint32_t addr) {
    asm volatile("ldmatrix.sync.aligned.m8n8.x4.shared.b16 {%0,%1,%2,%3}, [%4];"
                 : "=r"(a[0]), "=r"(a[1]), "=r"(a[2]), "=r"(a[3]) : "r"(addr));
}
__device__ __forceinline__ void cp16(uint32_t s_dst, const void* g_src) {
    asm volatile("cp.async.cg.shared.global [%0], [%1], 16;"
                 :: "r"(s_dst), "l"(g_src) : "memory");
}
__device__ __forceinline__ void cp_commit() {
    asm volatile("cp.async.commit_group;" ::: "memory");
}
__device__ __forceinline__ void cp_wait0() {
    asm volatile("cp.async.wait_group 0;" ::: "memory");
}
__device__ __forceinline__ uint32_t h2u(__half2 h) { return *(uint32_t*)&h; }

// ---------------------------------------------------------------------------
// Prep: premask W -> fp16 uint4 B-fragments; blocks >= 2048 do bias + nact
// ---------------------------------------------------------------------------
__global__ void prep_kernel(const float* __restrict__ w,
                            const float* __restrict__ wm,
                            const float* __restrict__ b,
                            const float* __restrict__ bm) {
    if (blockIdx.x >= 2048) {
        const int n = blockIdx.x - 2048, t = threadIdx.x;
        __shared__ int cnt;
        if (t == 0) cnt = 0;
        __syncthreads();
        float m = bm[n * DD + t];
        g_b[n * DD + t] = b[n * DD + t] * m;
        if (m != 0.f) atomicAdd(&cnt, 1);
        __syncthreads();
        if (t == 0) g_nact[n] = cnt;
        return;
    }
    int q = blockIdx.x * 256 + threadIdx.x;          // [0, 64*8*32*32)
    int lane = q & 31, t = (q >> 5) & 31, kc = (q >> 10) & 7, n = q >> 13;
    int j = t * 8 + (lane >> 2);
    int i0 = kc * 32 + 2 * (lane & 3);
    size_t base = ((size_t)n * DD + j) * DD + i0;
    uint4 r;
    {
        float2 v = *(const float2*)(w + base), m = *(const float2*)(wm + base);
        r.x = h2u(__floats2half2_rn(v.x * m.x, v.y * m.y));
    }
    {
        float2 v = *(const float2*)(w + base + 8), m = *(const float2*)(wm + base + 8);
        r.y = h2u(__floats2half2_rn(v.x * m.x, v.y * m.y));
    }
    {
        float2 v = *(const float2*)(w + base + 16), m = *(const float2*)(wm + base + 16);
        r.z = h2u(__floats2half2_rn(v.x * m.x, v.y * m.y));
    }
    {
        float2 v = *(const float2*)(w + base + 24), m = *(const float2*)(wm + base + 24);
        r.w = h2u(__floats2half2_rn(v.x * m.x, v.y * m.y));
    }
    g_wpack[q] = r;
}

// ---------------------------------------------------------------------------
// Fused 4-step recurrence, per-nact-class template. fp16 xs + ldmatrix.
// ---------------------------------------------------------------------------
extern __shared__ __align__(16) unsigned char smem_raw[];

template <int NT>
__global__ __launch_bounds__(THREADS, 2)
void blm_kernel(const float* __restrict__ x_in, float* __restrict__ x_out) {
    const int n = blockIdx.x >> 5;           // 64 groups x 32 batch tiles
    const int nact = g_nact[n];
    const int nk = (nact + 31) >> 5;
    if (NT == 8 ? (nk < 8) : (NT == 4 ? (nk > 4) : (nk != NT))) return;

    __half* xsh = (__half*)smem_raw;
    float* bsm = (float*)(smem_raw + BIAS_OFF);
    uint4* wbuf = (uint4*)(smem_raw + WBUF_OFF);
    const uint32_t smem_u = (uint32_t)__cvta_generic_to_shared(smem_raw);
    const uint32_t wb_u = smem_u + WBUF_OFF;

    const int tid = threadIdx.x;
    const int wid = tid >> 5, lane = tid & 31;
    const int mi = wid & 1, ni = wid >> 1;    // 2 (M) x 4 (N)
    const int r0 = (blockIdx.x & 31) * MTILE;

    bsm[tid] = g_b[n * DD + tid];

    // Load x tile (64 x 256) -> fp16 SMEM
    {
        const float4* xin4 = (const float4*)x_in;
        for (int v = tid; v < MTILE * 64; v += THREADS) {
            int row = v >> 6, c4 = v & 63;
            float4 f = xin4[((size_t)(r0 + row) * NN + n) * 64 + c4];
            uint2 h;
            h.x = h2u(__floats2half2_rn(f.x, f.y));
            h.y = h2u(__floats2half2_rn(f.z, f.w));
            *(uint2*)&xsh[row * XSH + c4 * 4] = h;
        }
    }
    __syncthreads();

    const uint4* wsrc = g_wpack + ((size_t)n << 13);

    // ldmatrix base addresses (per m-tile): row = mi*32+mt*16+(lane&15), koff = (lane>>4)*8
    const int row_l = (lane & 15);
    const int koff = (lane >> 4) * 8;
    uint32_t abase[2];
#pragma unroll
    for (int mt = 0; mt < 2; ++mt)
        abase[mt] = smem_u + ((mi * 32 + mt * 16 + row_l) * XSH + koff) * 2;

    const int rE = mi * 32 + (lane >> 2);     // epilogue row base
    const int cq = 2 * (lane & 3);
    const int nbase = ni * NT * 8;

    float acc[2][NT][4];

    for (int step = 0; step < NSTEPS; ++step) {
#pragma unroll
        for (int mt = 0; mt < 2; ++mt)
#pragma unroll
            for (int t = 0; t < NT; ++t)
#pragma unroll
                for (int q = 0; q < 4; ++q) acc[mt][t][q] = 0.f;

        // preload stage 0 (NT*128 uint4)
#pragma unroll
        for (int v = 0; v < NT / 2; ++v)
            cp16(wb_u + (tid + v * THREADS) * 16, wsrc + tid + v * THREADS);
        if (NT & 1) {
            if (tid < 128)
                cp16(wb_u + (tid + (NT / 2) * THREADS) * 16,
                     wsrc + tid + (NT / 2) * THREADS);
        }
        cp_commit(); cp_wait0();
        __syncthreads();

#pragma unroll
        for (int s = 0; s < NT; ++s) {
            const int buf = s & 1;
            if (s + 1 < NT) {                 // prefetch next k32 granule
                const uint4* src = wsrc + (size_t)(s + 1) * 1024;
                const uint32_t dst = wb_u + (buf ^ 1) * (NT * 128 * 16);
#pragma unroll
                for (int v = 0; v < NT / 2; ++v)
                    cp16(dst + (tid + v * THREADS) * 16, src + tid + v * THREADS);
                if (NT & 1) {
                    if (tid < 128)
                        cp16(dst + (tid + (NT / 2) * THREADS) * 16,
                             src + tid + (NT / 2) * THREADS);
                }
                cp_commit();
            }

            // A fragments: 4 ldmatrix.x4 (2 subs x 2 m-tiles)
            uint32_t a[2][2][4];
            const int kbyte = s * 64;         // s*32 halfs
#pragma unroll
            for (int sub = 0; sub < 2; ++sub)
#pragma unroll
                for (int mt = 0; mt < 2; ++mt)
                    ldmatrix4(a[sub][mt], abase[mt] + kbyte + sub * 32);

            // B: one LDS.128 per tile feeds 4 MMAs
            const uint4* bp = wbuf + buf * (NT * 128) + (ni * NT) * 32 + lane;
#pragma unroll
            for (int t = 0; t < NT; ++t) {
                uint4 bfr = bp[t * 32];
                mma16816(acc[0][t], a[0][0], bfr.x, bfr.y);
                mma16816(acc[1][t], a[0][1], bfr.x, bfr.y);
                mma16816(acc[0][t], a[1][0], bfr.z, bfr.w);
                mma16816(acc[1][t], a[1][1], bfr.z, bfr.w);
            }

            if (s + 1 < NT) cp_wait0();
            __syncthreads();                  // buffer reuse + A-read/epilogue order
        }

        // Epilogue: x += relu(acc + b) in fp32, stored back as fp16
#pragma unroll
        for (int mt = 0; mt < 2; ++mt) {
            const int r = rE + mt * 16;
#pragma unroll
            for (int t = 0; t < NT; ++t) {
                const int c = nbase + t * 8 + cq;
                float2 bv = *(const float2*)&bsm[c];
                {
                    __half2* p = (__half2*)&xsh[r * XSH + c];
                    float2 fx = __half22float2(*p);
                    fx.x += fmaxf(acc[mt][t][0] + bv.x, 0.f);
                    fx.y += fmaxf(acc[mt][t][1] + bv.y, 0.f);
                    *p = __floats2half2_rn(fx.x, fx.y);
                }
                {
                    __half2* p = (__half2*)&xsh[(r + 8) * XSH + c];
                    float2 fx = __half22float2(*p);
                    fx.x += fmaxf(acc[mt][t][2] + bv.x, 0.f);
                    fx.y += fmaxf(acc[mt][t][3] + bv.y, 0.f);
                    *p = __floats2half2_rn(fx.x, fx.y);
                }
            }
        }
        __syncthreads();
    }

    // Store: active cols from fp16 xs; inactive cols exact fp32 pass-through
    {
        const float4* xin4 = (const float4*)x_in;
        float4* xo = (float4*)x_out;
        for (int v = tid; v < MTILE * 64; v += THREADS) {
            int row = v >> 6, c4 = v & 63;
            size_t gi = ((size_t)(r0 + row) * NN + n) * 64 + c4;
            float4 f;
            if (c4 * 4 < nact) {
                uint2 h = *(const uint2*)&xsh[row * XSH + c4 * 4];
                float2 lo = __half22float2(*(__half2*)&h.x);
                float2 hi = __half22float2(*(__half2*)&h.y);
                f.x = lo.x; f.y = lo.y; f.z = hi.x; f.w = hi.y;
            } else {
                f = xin4[gi];
            }
            xo[gi] = f;
        }
    }
}

// ---------------------------------------------------------------------------
// Launch
// ---------------------------------------------------------------------------
template <int NT>
static void launch_class(const float* x, float* out) {
    const int smem = WBUF_OFF + 2 * NT * 2048;
    cudaFuncSetAttribute(blm_kernel<NT>,
                         cudaFuncAttributeMaxDynamicSharedMemorySize, smem);
    blm_kernel<NT><<<NN * (BB / MTILE), THREADS, smem>>>(x, out);
}

extern "C" void kernel_launch(void* const* d_in, const int* in_sizes, int n_in,
                              void* d_out, int out_size) {
    const float* x  = (const float*)d_in[0];
    const float* w  = (const float*)d_in[1];
    const float* b  = (const float*)d_in[2];
    const float* wm = (const float*)d_in[3];
    const float* bm = (const float*)d_in[4];
    float* out = (float*)d_out;

    prep_kernel<<<2048 + 64, 256>>>(w, wm, b, bm);
    launch_class<4>(x, out);
    launch_class<5>(x, out);
    launch_class<6>(x, out);
    launch_class<7>(x, out);
    launch_class<8>(x, out);
}

// round 8
// speedup vs baseline: 4.5016x; 1.2681x over previous
#include <cuda_runtime.h>
#include <cuda_fp16.h>
#include <cstdint>

#define BB      2048
#define NN      64
#define DD      256
#define NSTEPS  4
#define MTILE   64             // batch rows per CTA
#define THREADS 256            // 8 warps: 2 (M) x 4 (N)
#define XSH     264            // xs_h row stride in halfs (528B)

// SMEM layout (bytes)
#define XSH_BYTES  (MTILE * XSH * 2)      // 33792
#define BIAS_OFF   XSH_BYTES              // 1024 B fp32
#define WBUF_OFF   (BIAS_OFF + 1024)      // 34816
#define WBUF_BYTES 73728                  // 72 KB: full W (NT<=6) or stream ring
#define SMEM_TOTAL (WBUF_OFF + WBUF_BYTES)  // 108544

// Scratch (device globals)
// g_wpack[n][kc32][t][lane] (uint4): masked W fp16, m16n8k16 B-frag order.
//   j = t*8 + (lane>>2); i0 = kc32*32 + 2*(lane&3);
//   .x=(i0,i0+1) .y=(+8,+9) [sub0];  .z=(+16,+17) .w=(+24,+25) [sub1]
// Granule stride: 1024 uint4 (always 32 tiles). Active tiles are t < 4*NT
// (contiguous), so a compacted granule copy is 128*NT contiguous uint4.
__device__ __align__(16) uint4 g_wpack[NN * 8 * 32 * 32];
__device__ float g_b[NN * DD];
__device__ int   g_nact[NN];

// ---------------------------------------------------------------------------
// PTX helpers (plain sm_80+ PTX)
// ---------------------------------------------------------------------------
__device__ __forceinline__ void mma16816(float* d, const uint32_t* a,
                                         uint32_t b0, uint32_t b1) {
    asm volatile(
        "mma.sync.aligned.m16n8k16.row.col.f32.f16.f16.f32 "
        "{%0,%1,%2,%3}, {%4,%5,%6,%7}, {%8,%9}, {%0,%1,%2,%3};"
        : "+f"(d[0]), "+f"(d[1]), "+f"(d[2]), "+f"(d[3])
        : "r"(a[0]), "r"(a[1]), "r"(a[2]), "r"(a[3]), "r"(b0), "r"(b1));
}
__device__ __forceinline__ void ldmatrix4(uint32_t* a, uint32_t addr) {
    asm volatile("ldmatrix.sync.aligned.m8n8.x4.shared.b16 {%0,%1,%2,%3}, [%4];"
                 : "=r"(a[0]), "=r"(a[1]), "=r"(a[2]), "=r"(a[3]) : "r"(addr));
}
__device__ __forceinline__ void cp16(uint32_t s_dst, const void* g_src) {
    asm volatile("cp.async.cg.shared.global [%0], [%1], 16;"
                 :: "r"(s_dst), "l"(g_src) : "memory");
}
__device__ __forceinline__ void cp_commit() {
    asm volatile("cp.async.commit_group;" ::: "memory");
}
__device__ __forceinline__ void cp_wait0() {
    asm volatile("cp.async.wait_group 0;" ::: "memory");
}
__device__ __forceinline__ uint32_t h2u(__half2 h) { return *(uint32_t*)&h; }

// ---------------------------------------------------------------------------
// Prep: premask W -> fp16 uint4 B-fragments; blocks >= 2048 do bias + nact
// ---------------------------------------------------------------------------
__global__ void prep_kernel(const float* __restrict__ w,
                            const float* __restrict__ wm,
                            const float* __restrict__ b,
                            const float* __restrict__ bm) {
    if (blockIdx.x >= 2048) {
        const int n = blockIdx.x - 2048, t = threadIdx.x;
        __shared__ int cnt;
        if (t == 0) cnt = 0;
        __syncthreads();
        float m = bm[n * DD + t];
        g_b[n * DD + t] = b[n * DD + t] * m;
        if (m != 0.f) atomicAdd(&cnt, 1);
        __syncthreads();
        if (t == 0) g_nact[n] = cnt;
        return;
    }
    int q = blockIdx.x * 256 + threadIdx.x;          // [0, 64*8*32*32)
    int lane = q & 31, t = (q >> 5) & 31, kc = (q >> 10) & 7, n = q >> 13;
    int j = t * 8 + (lane >> 2);
    int i0 = kc * 32 + 2 * (lane & 3);
    size_t base = ((size_t)n * DD + j) * DD + i0;
    uint4 r;
    {
        float2 v = *(const float2*)(w + base), m = *(const float2*)(wm + base);
        r.x = h2u(__floats2half2_rn(v.x * m.x, v.y * m.y));
    }
    {
        float2 v = *(const float2*)(w + base + 8), m = *(const float2*)(wm + base + 8);
        r.y = h2u(__floats2half2_rn(v.x * m.x, v.y * m.y));
    }
    {
        float2 v = *(const float2*)(w + base + 16), m = *(const float2*)(wm + base + 16);
        r.z = h2u(__floats2half2_rn(v.x * m.x, v.y * m.y));
    }
    {
        float2 v = *(const float2*)(w + base + 24), m = *(const float2*)(wm + base + 24);
        r.w = h2u(__floats2half2_rn(v.x * m.x, v.y * m.y));
    }
    g_wpack[q] = r;
}

// ---------------------------------------------------------------------------
// Per-class step driver. RES: full W resident in SMEM (loaded by caller).
// NT==0: runtime streaming fallback.
// ---------------------------------------------------------------------------
extern __shared__ __align__(16) unsigned char smem_raw[];

template <int NT, bool RES>
__device__ __forceinline__ void run_steps(__half* xsh, const float* bsm,
                                          const uint4* wsrc, int nt_rt,
                                          int tid, int wid, int lane) {
    const int nt = (NT > 0) ? NT : nt_rt;
    uint4* wbuf = (uint4*)(smem_raw + WBUF_OFF);
    const uint32_t smem_u = (uint32_t)__cvta_generic_to_shared(smem_raw);
    const uint32_t wb_u = smem_u + WBUF_OFF;

    const int mi = wid & 1, ni = wid >> 1;    // 2 (M) x 4 (N)
    const int row_l = (lane & 15);
    const int koff = (lane >> 4) * 8;
    uint32_t abase[2];
#pragma unroll
    for (int mt = 0; mt < 2; ++mt)
        abase[mt] = smem_u + ((mi * 32 + mt * 16 + row_l) * XSH + koff) * 2;

    const int rE = mi * 32 + (lane >> 2);
    const int cq = 2 * (lane & 3);
    const int nbase = ni * nt * 8;

    if (RES) {
        // Load ALL active W once: NT granules x 128*NT contiguous uint4
        const int per_g = 128 * nt;
        for (int v = tid; v < nt * per_g; v += THREADS) {
            int g = v / per_g, within = v - g * per_g;
            cp16(wb_u + v * 16, wsrc + g * 1024 + within);
        }
        cp_commit(); cp_wait0();
    }
    __syncthreads();

    float acc[2][(NT > 0) ? NT : 8][4];

    for (int step = 0; step < NSTEPS; ++step) {
#pragma unroll
        for (int mt = 0; mt < 2; ++mt)
#pragma unroll
            for (int t = 0; t < ((NT > 0) ? NT : 8); ++t)
#pragma unroll
                for (int q = 0; q < 4; ++q)
                    if (NT > 0 || t < nt_rt) acc[mt][t][q] = 0.f;

        if (!RES) {   // preload stage 0 of the stream
            for (int v = tid; v < 128 * nt; v += THREADS)
                cp16(wb_u + v * 16, wsrc + v);
            cp_commit(); cp_wait0();
            __syncthreads();
        }

#pragma unroll
        for (int s = 0; s < ((NT > 0) ? NT : 8); ++s) {
            if (NT == 0 && s >= nt_rt) break;
            const int buf = s & 1;
            if (!RES && s + 1 < nt) {        // prefetch next granule
                const uint4* src = wsrc + (size_t)(s + 1) * 1024;
                const uint32_t dst = wb_u + (buf ^ 1) * (1024 * 16);
                for (int v = tid; v < 128 * nt; v += THREADS)
                    cp16(dst + v * 16, src + v);
                cp_commit();
            }

            // A fragments: 4 ldmatrix.x4 (2 k16-subs x 2 m-tiles)
            uint32_t a[2][2][4];
            const int kbyte = s * 64;
#pragma unroll
            for (int sub = 0; sub < 2; ++sub)
#pragma unroll
                for (int mt = 0; mt < 2; ++mt)
                    ldmatrix4(a[sub][mt], abase[mt] + kbyte + sub * 32);

            // B: resident at s*128*nt; stream ring at buf*1024
            const uint4* bp = (RES ? wbuf + s * (128 * nt)
                                   : wbuf + buf * 1024) + ni * nt * 32 + lane;
#pragma unroll
            for (int t = 0; t < ((NT > 0) ? NT : 8); ++t) {
                if (NT == 0 && t >= nt_rt) break;
                uint4 bfr = bp[t * 32];
                mma16816(acc[0][t], a[0][0], bfr.x, bfr.y);
                mma16816(acc[1][t], a[0][1], bfr.x, bfr.y);
                mma16816(acc[0][t], a[1][0], bfr.z, bfr.w);
                mma16816(acc[1][t], a[1][1], bfr.z, bfr.w);
            }

            if (!RES) {
                if (s + 1 < nt) cp_wait0();
                __syncthreads();             // ring-buffer reuse ordering
            }
        }

        __syncthreads();   // all ldmatrix reads done before epilogue writes

        // Epilogue: x += relu(acc + b) in fp32, stored back as fp16
#pragma unroll
        for (int mt = 0; mt < 2; ++mt) {
            const int r = rE + mt * 16;
#pragma unroll
            for (int t = 0; t < ((NT > 0) ? NT : 8); ++t) {
                if (NT == 0 && t >= nt_rt) break;
                const int c = nbase + t * 8 + cq;
                float2 bv = *(const float2*)&bsm[c];
                {
                    __half2* p = (__half2*)&xsh[r * XSH + c];
                    float2 fx = __half22float2(*p);
                    fx.x += fmaxf(acc[mt][t][0] + bv.x, 0.f);
                    fx.y += fmaxf(acc[mt][t][1] + bv.y, 0.f);
                    *p = __floats2half2_rn(fx.x, fx.y);
                }
                {
                    __half2* p = (__half2*)&xsh[(r + 8) * XSH + c];
                    float2 fx = __half22float2(*p);
                    fx.x += fmaxf(acc[mt][t][2] + bv.x, 0.f);
                    fx.y += fmaxf(acc[mt][t][3] + bv.y, 0.f);
                    *p = __floats2half2_rn(fx.x, fx.y);
                }
            }
        }
        __syncthreads();   // epilogue visible before next step / final store
    }
}

// Heavy-first rank -> group mapping (class c = n%5 descending; NT=8 first)
__device__ __forceinline__ int rank_to_n(int r) {
    if (r < 12) return 4 + 5 * r;
    if (r < 25) return 3 + 5 * (r - 12);
    if (r < 38) return 2 + 5 * (r - 25);
    if (r < 51) return 1 + 5 * (r - 38);
    return 5 * (r - 51);
}

__global__ __launch_bounds__(THREADS, 2)
void blm_all_kernel(const float* __restrict__ x_in, float* __restrict__ x_out) {
    const int rank = blockIdx.x >> 5;
    const int n = rank_to_n(rank);
    const int r0 = (blockIdx.x & 31) * MTILE;
    const int nact = g_nact[n];
    const int nk = nact >> 5;

    __half* xsh = (__half*)smem_raw;
    float* bsm = (float*)(smem_raw + BIAS_OFF);
    const int tid = threadIdx.x;
    const int wid = tid >> 5, lane = tid & 31;

    bsm[tid] = g_b[n * DD + tid];

    // Load x tile (64 x 256) -> fp16 SMEM
    {
        const float4* xin4 = (const float4*)x_in;
        for (int v = tid; v < MTILE * 64; v += THREADS) {
            int row = v >> 6, c4 = v & 63;
            float4 f = xin4[((size_t)(r0 + row) * NN + n) * 64 + c4];
            uint2 h;
            h.x = h2u(__floats2half2_rn(f.x, f.y));
            h.y = h2u(__floats2half2_rn(f.z, f.w));
            *(uint2*)&xsh[row * XSH + c4 * 4] = h;
        }
    }
    // note: run_steps starts with __syncthreads() covering xs/bias visibility

    const uint4* wsrc = g_wpack + ((size_t)n << 13);
    switch (nk) {
        case 4: run_steps<4, true >(xsh, bsm, wsrc, nk, tid, wid, lane); break;
        case 5: run_steps<5, true >(xsh, bsm, wsrc, nk, tid, wid, lane); break;
        case 6: run_steps<6, true >(xsh, bsm, wsrc, nk, tid, wid, lane); break;
        case 7: run_steps<7, false>(xsh, bsm, wsrc, nk, tid, wid, lane); break;
        case 8: run_steps<8, false>(xsh, bsm, wsrc, nk, tid, wid, lane); break;
        default: run_steps<0, false>(xsh, bsm, wsrc, nk, tid, wid, lane); break;
    }

    // Store: active cols from fp16 xs; inactive cols exact fp32 pass-through
    {
        const float4* xin4 = (const float4*)x_in;
        float4* xo = (float4*)x_out;
        for (int v = tid; v < MTILE * 64; v += THREADS) {
            int row = v >> 6, c4 = v & 63;
            size_t gi = ((size_t)(r0 + row) * NN + n) * 64 + c4;
            float4 f;
            if (c4 * 4 < nact) {
                uint2 h = *(const uint2*)&xsh[row * XSH + c4 * 4];
                float2 lo = __half22float2(*(__half2*)&h.x);
                float2 hi = __half22float2(*(__half2*)&h.y);
                f.x = lo.x; f.y = lo.y; f.z = hi.x; f.w = hi.y;
            } else {
                f = xin4[gi];
            }
            xo[gi] = f;
        }
    }
}

// ---------------------------------------------------------------------------
// Launch
// ---------------------------------------------------------------------------
extern "C" void kernel_launch(void* const* d_in, const int* in_sizes, int n_in,
                              void* d_out, int out_size) {
    const float* x  = (const float*)d_in[0];
    const float* w  = (const float*)d_in[1];
    const float* b  = (const float*)d_in[2];
    const float* wm = (const float*)d_in[3];
    const float* bm = (const float*)d_in[4];
    float* out = (float*)d_out;

    cudaFuncSetAttribute(blm_all_kernel,
                         cudaFuncAttributeMaxDynamicSharedMemorySize, SMEM_TOTAL);

    prep_kernel<<<2048 + 64, 256>>>(w, wm, b, bm);
    blm_all_kernel<<<NN * (BB / MTILE), THREADS, SMEM_TOTAL>>>(x, out);
}

// round 9
// speedup vs baseline: 5.3070x; 1.1789x over previous
#include <cuda_runtime.h>
#include <cuda_fp16.h>
#include <cstdint>

#define BB      2048
#define NN      64
#define DD      256
#define NSTEPS  4
#define MTILE   64             // batch rows per CTA
#define THREADS 512            // 16 warps: 4 (M) x 4 (N)
#define XSH     264            // xs_h row stride in halfs (528B)

// SMEM layout (bytes)
#define XSH_BYTES  (MTILE * XSH * 2)      // 33792
#define BIAS_OFF   XSH_BYTES              // 1024 B fp32
#define WBUF_OFF   (BIAS_OFF + 1024)      // 34816
#define WBUF_BYTES 73728                  // 72 KB: full W (NT<=6) or stream ring
#define SMEM_TOTAL (WBUF_OFF + WBUF_BYTES)  // 108544 <= 113664 (2 CTAs/SM)

// Scratch (device globals)
// g_wpack[n][kc32][t][lane] (uint4): masked W fp16, m16n8k16 B-frag order.
//   j = t*8 + (lane>>2); i0 = kc32*32 + 2*(lane&3);
//   .x=(i0,i0+1) .y=(+8,+9) [sub0];  .z=(+16,+17) .w=(+24,+25) [sub1]
// Granule stride: 1024 uint4 (always 32 tiles); active tiles t < 4*NT contiguous.
__device__ __align__(16) uint4 g_wpack[NN * 8 * 32 * 32];
__device__ float g_b[NN * DD];
__device__ int   g_nact[NN];

// ---------------------------------------------------------------------------
// PTX helpers (plain sm_80+ PTX)
// ---------------------------------------------------------------------------
__device__ __forceinline__ void mma16816(float* d, const uint32_t* a,
                                         uint32_t b0, uint32_t b1) {
    asm volatile(
        "mma.sync.aligned.m16n8k16.row.col.f32.f16.f16.f32 "
        "{%0,%1,%2,%3}, {%4,%5,%6,%7}, {%8,%9}, {%0,%1,%2,%3};"
        : "+f"(d[0]), "+f"(d[1]), "+f"(d[2]), "+f"(d[3])
        : "r"(a[0]), "r"(a[1]), "r"(a[2]), "r"(a[3]), "r"(b0), "r"(b1));
}
__device__ __forceinline__ void ldmatrix4(uint32_t* a, uint32_t addr) {
    asm volatile("ldmatrix.sync.aligned.m8n8.x4.shared.b16 {%0,%1,%2,%3}, [%4];"
                 : "=r"(a[0]), "=r"(a[1]), "=r"(a[2]), "=r"(a[3]) : "r"(addr));
}
__device__ __forceinline__ void cp16(uint32_t s_dst, const void* g_src) {
    asm volatile("cp.async.cg.shared.global [%0], [%1], 16;"
                 :: "r"(s_dst), "l"(g_src) : "memory");
}
__device__ __forceinline__ void cp_commit() {
    asm volatile("cp.async.commit_group;" ::: "memory");
}
__device__ __forceinline__ void cp_wait0() {
    asm volatile("cp.async.wait_group 0;" ::: "memory");
}
__device__ __forceinline__ uint32_t h2u(__half2 h) { return *(uint32_t*)&h; }

// ---------------------------------------------------------------------------
// Prep: premask W -> fp16 uint4 B-fragments; blocks >= 2048 do bias + nact
// ---------------------------------------------------------------------------
__global__ void prep_kernel(const float* __restrict__ w,
                            const float* __restrict__ wm,
                            const float* __restrict__ b,
                            const float* __restrict__ bm) {
    if (blockIdx.x >= 2048) {
        const int n = blockIdx.x - 2048, t = threadIdx.x;
        __shared__ int cnt;
        if (t == 0) cnt = 0;
        __syncthreads();
        float m = bm[n * DD + t];
        g_b[n * DD + t] = b[n * DD + t] * m;
        if (m != 0.f) atomicAdd(&cnt, 1);
        __syncthreads();
        if (t == 0) g_nact[n] = cnt;
        return;
    }
    int q = blockIdx.x * 256 + threadIdx.x;          // [0, 64*8*32*32)
    int lane = q & 31, t = (q >> 5) & 31, kc = (q >> 10) & 7, n = q >> 13;
    int j = t * 8 + (lane >> 2);
    int i0 = kc * 32 + 2 * (lane & 3);
    size_t base = ((size_t)n * DD + j) * DD + i0;
    uint4 r;
    {
        float2 v = *(const float2*)(w + base), m = *(const float2*)(wm + base);
        r.x = h2u(__floats2half2_rn(v.x * m.x, v.y * m.y));
    }
    {
        float2 v = *(const float2*)(w + base + 8), m = *(const float2*)(wm + base + 8);
        r.y = h2u(__floats2half2_rn(v.x * m.x, v.y * m.y));
    }
    {
        float2 v = *(const float2*)(w + base + 16), m = *(const float2*)(wm + base + 16);
        r.z = h2u(__floats2half2_rn(v.x * m.x, v.y * m.y));
    }
    {
        float2 v = *(const float2*)(w + base + 24), m = *(const float2*)(wm + base + 24);
        r.w = h2u(__floats2half2_rn(v.x * m.x, v.y * m.y));
    }
    g_wpack[q] = r;
}

// ---------------------------------------------------------------------------
// Per-class step driver. RES: full W resident in SMEM. NT==0: runtime fallback.
// Warp layout: mi = wid&3 (one m16 tile: rows mi*16..+15), ni = wid>>2.
// ---------------------------------------------------------------------------
extern __shared__ __align__(16) unsigned char smem_raw[];

template <int NT, bool RES>
__device__ __forceinline__ void run_steps(__half* xsh, const float* bsm,
                                          const uint4* wsrc, int nt_rt,
                                          int tid, int wid, int lane) {
    const int nt = (NT > 0) ? NT : nt_rt;
    uint4* wbuf = (uint4*)(smem_raw + WBUF_OFF);
    const uint32_t smem_u = (uint32_t)__cvta_generic_to_shared(smem_raw);
    const uint32_t wb_u = smem_u + WBUF_OFF;

    const int mi = wid & 3, ni = wid >> 2;    // 4 (M) x 4 (N)
    const int row_l = (lane & 15);
    const int koff = (lane >> 4) * 8;
    const uint32_t abase = smem_u + ((mi * 16 + row_l) * XSH + koff) * 2;

    const int rE = mi * 16 + (lane >> 2);
    const int cq = 2 * (lane & 3);
    const int nbase = ni * nt * 8;

    if (RES) {
        // Load ALL active W once: nt granules x 128*nt contiguous uint4
        const int per_g = 128 * nt;
        for (int v = tid; v < nt * per_g; v += THREADS) {
            int g = v / per_g, within = v - g * per_g;
            cp16(wb_u + v * 16, wsrc + g * 1024 + within);
        }
        cp_commit(); cp_wait0();
    }
    __syncthreads();

    float acc[(NT > 0) ? NT : 8][4];

    for (int step = 0; step < NSTEPS; ++step) {
#pragma unroll
        for (int t = 0; t < ((NT > 0) ? NT : 8); ++t)
#pragma unroll
            for (int q = 0; q < 4; ++q)
                if (NT > 0 || t < nt_rt) acc[t][q] = 0.f;

        if (!RES) {   // preload stage 0 of the stream
            for (int v = tid; v < 128 * nt; v += THREADS)
                cp16(wb_u + v * 16, wsrc + v);
            cp_commit(); cp_wait0();
            __syncthreads();
        }

#pragma unroll
        for (int s = 0; s < ((NT > 0) ? NT : 8); ++s) {
            if (NT == 0 && s >= nt_rt) break;
            const int buf = s & 1;
            if (!RES && s + 1 < nt) {        // prefetch next granule
                const uint4* src = wsrc + (size_t)(s + 1) * 1024;
                const uint32_t dst = wb_u + (buf ^ 1) * (1024 * 16);
                for (int v = tid; v < 128 * nt; v += THREADS)
                    cp16(dst + v * 16, src + v);
                cp_commit();
            }

            // A fragments: 2 ldmatrix.x4 (k16 subs 0,1) for this warp's m16 tile
            uint32_t a[2][4];
            const int kbyte = s * 64;
            ldmatrix4(a[0], abase + kbyte);
            ldmatrix4(a[1], abase + kbyte + 32);

            // B: resident at s*128*nt; stream ring at buf*1024
            const uint4* bp = (RES ? wbuf + s * (128 * nt)
                                   : wbuf + buf * 1024) + ni * nt * 32 + lane;
#pragma unroll
            for (int t = 0; t < ((NT > 0) ? NT : 8); ++t) {
                if (NT == 0 && t >= nt_rt) break;
                uint4 bfr = bp[t * 32];
                mma16816(acc[t], a[0], bfr.x, bfr.y);
                mma16816(acc[t], a[1], bfr.z, bfr.w);
            }

            if (!RES) {
                if (s + 1 < nt) cp_wait0();
                __syncthreads();             // ring-buffer reuse ordering
            }
        }

        __syncthreads();   // all ldmatrix reads done before epilogue writes

        // Epilogue: x += relu(acc + b) in fp32, stored back as fp16
#pragma unroll
        for (int t = 0; t < ((NT > 0) ? NT : 8); ++t) {
            if (NT == 0 && t >= nt_rt) break;
            const int c = nbase + t * 8 + cq;
            float2 bv = *(const float2*)&bsm[c];
            {
                __half2* p = (__half2*)&xsh[rE * XSH + c];
                float2 fx = __half22float2(*p);
                fx.x += fmaxf(acc[t][0] + bv.x, 0.f);
                fx.y += fmaxf(acc[t][1] + bv.y, 0.f);
                *p = __floats2half2_rn(fx.x, fx.y);
            }
            {
                __half2* p = (__half2*)&xsh[(rE + 8) * XSH + c];
                float2 fx = __half22float2(*p);
                fx.x += fmaxf(acc[t][2] + bv.x, 0.f);
                fx.y += fmaxf(acc[t][3] + bv.y, 0.f);
                *p = __floats2half2_rn(fx.x, fx.y);
            }
        }
        __syncthreads();   // epilogue visible before next step / final store
    }
}

// Heavy-first rank -> group mapping (class c = n%5 descending; NT=8 first)
__device__ __forceinline__ int rank_to_n(int r) {
    if (r < 12) return 4 + 5 * r;
    if (r < 25) return 3 + 5 * (r - 12);
    if (r < 38) return 2 + 5 * (r - 25);
    if (r < 51) return 1 + 5 * (r - 38);
    return 5 * (r - 51);
}

__global__ __launch_bounds__(THREADS, 2)
void blm_all_kernel(const float* __restrict__ x_in, float* __restrict__ x_out) {
    const int rank = blockIdx.x >> 5;
    const int n = rank_to_n(rank);
    const int r0 = (blockIdx.x & 31) * MTILE;
    const int nact = g_nact[n];
    const int nk = nact >> 5;

    __half* xsh = (__half*)smem_raw;
    float* bsm = (float*)(smem_raw + BIAS_OFF);
    const int tid = threadIdx.x;
    const int wid = tid >> 5, lane = tid & 31;

    if (tid < DD) bsm[tid] = g_b[n * DD + tid];

    // Load x tile (64 x 256) -> fp16 SMEM
    {
        const float4* xin4 = (const float4*)x_in;
        for (int v = tid; v < MTILE * 64; v += THREADS) {
            int row = v >> 6, c4 = v & 63;
            float4 f = xin4[((size_t)(r0 + row) * NN + n) * 64 + c4];
            uint2 h;
            h.x = h2u(__floats2half2_rn(f.x, f.y));
            h.y = h2u(__floats2half2_rn(f.z, f.w));
            *(uint2*)&xsh[row * XSH + c4 * 4] = h;
        }
    }
    // run_steps starts with __syncthreads() covering xs/bias visibility

    const uint4* wsrc = g_wpack + ((size_t)n << 13);
    switch (nk) {
        case 4: run_steps<4, true >(xsh, bsm, wsrc, nk, tid, wid, lane); break;
        case 5: run_steps<5, true >(xsh, bsm, wsrc, nk, tid, wid, lane); break;
        case 6: run_steps<6, true >(xsh, bsm, wsrc, nk, tid, wid, lane); break;
        case 7: run_steps<7, false>(xsh, bsm, wsrc, nk, tid, wid, lane); break;
        case 8: run_steps<8, false>(xsh, bsm, wsrc, nk, tid, wid, lane); break;
        default: run_steps<0, false>(xsh, bsm, wsrc, nk, tid, wid, lane); break;
    }

    // Store: active cols from fp16 xs; inactive cols exact fp32 pass-through
    {
        const float4* xin4 = (const float4*)x_in;
        float4* xo = (float4*)x_out;
        for (int v = tid; v < MTILE * 64; v += THREADS) {
            int row = v >> 6, c4 = v & 63;
            size_t gi = ((size_t)(r0 + row) * NN + n) * 64 + c4;
            float4 f;
            if (c4 * 4 < nact) {
                uint2 h = *(const uint2*)&xsh[row * XSH + c4 * 4];
                float2 lo = __half22float2(*(__half2*)&h.x);
                float2 hi = __half22float2(*(__half2*)&h.y);
                f.x = lo.x; f.y = lo.y; f.z = hi.x; f.w = hi.y;
            } else {
                f = xin4[gi];
            }
            xo[gi] = f;
        }
    }
}

// ---------------------------------------------------------------------------
// Launch
// ---------------------------------------------------------------------------
extern "C" void kernel_launch(void* const* d_in, const int* in_sizes, int n_in,
                              void* d_out, int out_size) {
    const float* x  = (const float*)d_in[0];
    const float* w  = (const float*)d_in[1];
    const float* b  = (const float*)d_in[2];
    const float* wm = (const float*)d_in[3];
    const float* bm = (const float*)d_in[4];
    float* out = (float*)d_out;

    cudaFuncSetAttribute(blm_all_kernel,
                         cudaFuncAttributeMaxDynamicSharedMemorySize, SMEM_TOTAL);

    prep_kernel<<<2048 + 64, 256>>>(w, wm, b, bm);
    blm_all_kernel<<<NN * (BB / MTILE), THREADS, SMEM_TOTAL>>>(x, out);
}